// round 6
// baseline (speedup 1.0000x reference)
#include <cuda_runtime.h>
#include <cstdint>

// GraphConvolution on GB300:
//   Wu = sum_{c<=r} u_weight[c]; Wv likewise          (k_prep)
//   su/sv = (u|v) @ W  -> stored tf32-rounded, MMA-fragment-packed (k_feat)
//   top = deg[:nu] * (adj @ sv); bot = deg[nu:] * (adjT @ su)
//        -> k_gemm<GZ>: tf32 mma.sync, 3-stage cp.async, split-K=4
//   out = concat(top,bot) + bias                       (k_final)

#define IN_DIM 128
#define HID    64
#define NMAX   8192
#define SPLITS 4
#define STAGES 3

// A-tile SMEM strides (conflict-free fragment LDS, verified):
//   GZ=0 layout [m][k], stride 20  (banks 20g+t mod 32 distinct)
//   GZ=1 layout [k][m], stride 136 (banks 8t+g  mod 32 distinct)
#define AS0_STRIDE 20
#define AS1_STRIDE 136
#define AS_FLOATS  2560   // max(128*20, 16*136)
// B-tile: packed fragment layout, 16k x 64h = 1024 floats, no padding.
#define BS_FLOATS  1024

// su/sv stored packed: idx(k,h) = (k/16)*1024 + h*16 + (k%4)*4 + ((k/4)%4)
// -> LDS128 at h*16 + 4t yields k = {t, t+4, t+8, t+12} for column h.
__device__ __align__(16) float g_Wu[IN_DIM * HID];
__device__ __align__(16) float g_Wv[IN_DIM * HID];
__device__ __align__(16) float g_suB[NMAX * HID];
__device__ __align__(16) float g_svB[NMAX * HID];
__device__ __align__(16) float g_part[2 * SPLITS * NMAX * HID];

__device__ __forceinline__ float to_tf32(float x) {
    asm("cvt.rna.tf32.f32 %0, %0;" : "+f"(x));
    return x;
}
__device__ __forceinline__ uint32_t tf32_bits(float x) {
    return __float_as_uint(to_tf32(x));
}
__device__ __forceinline__ void cp16(void* dst_smem, const void* src_gmem) {
    uint32_t d = (uint32_t)__cvta_generic_to_shared(dst_smem);
    asm volatile("cp.async.cg.shared.global [%0], [%1], 16;\n" :: "r"(d), "l"(src_gmem));
}

// ---------------------------------------------------------------------------
__global__ void k_prep(const float* __restrict__ uw, const float* __restrict__ vw,
                       const int* __restrict__ rp) {
    const int r = rp[0];
    const int n = IN_DIM * HID;
    for (int i = blockIdx.x * blockDim.x + threadIdx.x; i < n; i += gridDim.x * blockDim.x) {
        float a = 0.f, b = 0.f;
        for (int c = 0; c <= r; c++) { a += uw[c * n + i]; b += vw[c * n + i]; }
        g_Wu[i] = a; g_Wv[i] = b;
    }
}

// ---------------------------------------------------------------------------
// su / sv:  X[rows,128] @ W[128,64], output tf32-rounded in packed layout.
#define WT_STRIDE 132
__global__ __launch_bounds__(256)
void k_feat(const float* __restrict__ u, const float* __restrict__ v, int nu, int nv) {
    __shared__ float Wt[HID * WT_STRIDE];   // [h][k]
    __shared__ float Us[32 * IN_DIM];
    const float* X; const float* W; float* out; int rows;
    if (blockIdx.y == 0) { X = u; W = g_Wu; out = g_suB; rows = nu; }
    else                 { X = v; W = g_Wv; out = g_svB; rows = nv; }

    const int tid = threadIdx.x;
    const int r0  = blockIdx.x * 32;
    if (r0 >= rows) return;

    for (int i = tid; i < IN_DIM * HID; i += 256) {
        const int k = i >> 6, h = i & 63;           // W is [k][h]
        Wt[h * WT_STRIDE + k] = W[i];
    }
    for (int i = tid; i < 32 * IN_DIM; i += 256)  Us[i] = X[(size_t)r0 * IN_DIM + i];
    __syncthreads();

    const int h  = tid & 63;
    const int rg = (tid >> 6) * 8;   // 8 rows per thread
    float acc[8];
    #pragma unroll
    for (int r = 0; r < 8; r++) acc[r] = 0.f;

    #pragma unroll 4
    for (int k = 0; k < IN_DIM; k += 4) {
        const float4 wq = *(const float4*)&Wt[h * WT_STRIDE + k];
        #pragma unroll
        for (int r = 0; r < 8; r++) {
            const float4 uq = *(const float4*)&Us[(rg + r) * IN_DIM + k];
            acc[r] += uq.x * wq.x + uq.y * wq.y + uq.z * wq.z + uq.w * wq.w;
        }
    }
    #pragma unroll
    for (int r = 0; r < 8; r++) {
        const int k = r0 + rg + r;   // global row index = GEMM k index
        const int idx = (k >> 4) * 1024 + h * 16 + (k & 3) * 4 + ((k >> 2) & 3);
        out[idx] = to_tf32(acc[r]);
    }
}

// ---------------------------------------------------------------------------
// GZ=0: C[m,h] = sum_k adj[m*nv + k]  * sv[k,h]
// GZ=1: C[m,h] = sum_k adj[k*nv + m]  * su[k,h]
// BM=128, BN=64, BK=16; 8 warps as 4(M)x2(N), warp 32x32 via m16n8k8 tf32.
// 3-stage cp.async pipeline (empty commit at tail keeps FIFO accounting).
template <int GZ>
__global__ __launch_bounds__(256, 4)
void k_gemm(const float* __restrict__ adj, int nu, int nv) {
    const int K = GZ ? nu : nv;
    const float* __restrict__ B = GZ ? g_suB : g_svB;

    const int m0     = blockIdx.x * 128;
    const int klen   = K / SPLITS;
    const int k0     = blockIdx.y * klen;
    const int ntiles = klen / 16;

    __shared__ __align__(16) float As[STAGES][AS_FLOATS];
    __shared__ __align__(16) float Bs[STAGES][BS_FLOATS];

    const int tid  = threadIdx.x;
    const int warp = tid >> 5;
    const int lane = tid & 31;
    const int g    = lane >> 2;
    const int t    = lane & 3;
    const int wm   = (warp >> 1) * 32;
    const int wn   = (warp & 1) * 32;

    float acc[2][4][4];
    #pragma unroll
    for (int i = 0; i < 2; i++)
        #pragma unroll
        for (int j = 0; j < 4; j++)
            #pragma unroll
            for (int q = 0; q < 4; q++) acc[i][j][q] = 0.f;

    auto issue = [&](int s, int kt) {
        const int kbase = k0 + kt * 16;
        // B tile: 4KB contiguous packed block, 1 chunk per thread
        cp16(&Bs[s][tid * 4], &B[(size_t)(kbase >> 4) * 1024 + tid * 4]);
        if (GZ == 0) {  // A tile [m][k]
            const int r = tid >> 2, c = tid & 3;
            cp16(&As[s][r * AS0_STRIDE + c * 4],
                 &adj[(size_t)(m0 + r) * nv + kbase + c * 4]);
            cp16(&As[s][(r + 64) * AS0_STRIDE + c * 4],
                 &adj[(size_t)(m0 + r + 64) * nv + kbase + c * 4]);
        } else {        // A tile [k][m]
            const int row = tid >> 4, ch = tid & 15;
            cp16(&As[s][row * AS1_STRIDE + ch * 4],
                 &adj[(size_t)(kbase + row) * nv + m0 + ch * 4]);
            cp16(&As[s][row * AS1_STRIDE + (ch + 16) * 4],
                 &adj[(size_t)(kbase + row) * nv + m0 + (ch + 16) * 4]);
        }
        asm volatile("cp.async.commit_group;\n" ::);
    };

    #pragma unroll
    for (int s = 0; s < STAGES - 1; s++) issue(s, s);

    for (int kt = 0; kt < ntiles; kt++) {
        const int s = kt % STAGES;
        asm volatile("cp.async.wait_group %0;\n" :: "n"(STAGES - 2));
        __syncthreads();

        const int nk = kt + STAGES - 1;
        if (nk < ntiles) issue(nk % STAGES, nk);
        else             asm volatile("cp.async.commit_group;\n" ::);

        const float* __restrict__ Asb = As[s];
        const float* __restrict__ Bsb = Bs[s];

        // B fragments for all 4 ntiles, BOTH kk steps: 4 conflict-free LDS128.
        // float4 components = k {t, t+4, t+8, t+12} for column wn+8j+g.
        float4 bq[4];
        #pragma unroll
        for (int j = 0; j < 4; j++)
            bq[j] = *(const float4*)&Bsb[(wn + 8 * j + g) * 16 + 4 * t];

        #pragma unroll
        for (int kk = 0; kk < 16; kk += 8) {
            uint32_t af[2][4];
            #pragma unroll
            for (int i = 0; i < 2; i++) {
                const int mb = wm + i * 16 + g;
                if (GZ == 0) {
                    af[i][0] = tf32_bits(Asb[(mb)     * AS0_STRIDE + kk + t]);
                    af[i][1] = tf32_bits(Asb[(mb + 8) * AS0_STRIDE + kk + t]);
                    af[i][2] = tf32_bits(Asb[(mb)     * AS0_STRIDE + kk + t + 4]);
                    af[i][3] = tf32_bits(Asb[(mb + 8) * AS0_STRIDE + kk + t + 4]);
                } else {
                    af[i][0] = tf32_bits(Asb[(kk + t)     * AS1_STRIDE + mb]);
                    af[i][1] = tf32_bits(Asb[(kk + t)     * AS1_STRIDE + mb + 8]);
                    af[i][2] = tf32_bits(Asb[(kk + t + 4) * AS1_STRIDE + mb]);
                    af[i][3] = tf32_bits(Asb[(kk + t + 4) * AS1_STRIDE + mb + 8]);
                }
            }
            #pragma unroll
            for (int i = 0; i < 2; i++)
                #pragma unroll
                for (int j = 0; j < 4; j++) {
                    const uint32_t b0 = __float_as_uint(kk ? bq[j].z : bq[j].x);
                    const uint32_t b1 = __float_as_uint(kk ? bq[j].w : bq[j].y);
                    asm volatile(
                        "mma.sync.aligned.m16n8k8.row.col.f32.tf32.tf32.f32 "
                        "{%0,%1,%2,%3}, {%4,%5,%6,%7}, {%8,%9}, {%0,%1,%2,%3};"
                        : "+f"(acc[i][j][0]), "+f"(acc[i][j][1]),
                          "+f"(acc[i][j][2]), "+f"(acc[i][j][3])
                        : "r"(af[i][0]), "r"(af[i][1]), "r"(af[i][2]), "r"(af[i][3]),
                          "r"(b0), "r"(b1));
                }
        }
        __syncthreads();
    }

    float* __restrict__ P = &g_part[(size_t)((GZ * SPLITS + blockIdx.y) * NMAX) * HID];
    #pragma unroll
    for (int i = 0; i < 2; i++) {
        #pragma unroll
        for (int j = 0; j < 4; j++) {
            const int m = m0 + wm + i * 16 + g;
            const int n = wn + j * 8 + 2 * t;
            *(float2*)&P[(size_t)m * HID + n]       = make_float2(acc[i][j][0], acc[i][j][1]);
            *(float2*)&P[(size_t)(m + 8) * HID + n] = make_float2(acc[i][j][2], acc[i][j][3]);
        }
    }
}

// ---------------------------------------------------------------------------
__global__ void k_final(const float* __restrict__ degree, const float* __restrict__ bias,
                        float* __restrict__ out, int nu, int nv) {
    const int total = (nu + nv) * HID;
    const int idx = blockIdx.x * blockDim.x + threadIdx.x;
    if (idx >= total) return;
    const int row = idx >> 6;
    const int h   = idx & 63;
    const int gg  = (row < nu) ? 0 : 1;
    const int rr  = gg ? (row - nu) : row;
    float s = 0.f;
    #pragma unroll
    for (int sp = 0; sp < SPLITS; sp++)
        s += g_part[((size_t)(gg * SPLITS + sp) * NMAX + rr) * HID + h];
    out[idx] = degree[row] * s + bias[h];
}

// ---------------------------------------------------------------------------
extern "C" void kernel_launch(void* const* d_in, const int* in_sizes, int n_in,
                              void* d_out, int out_size) {
    const float* u      = (const float*)d_in[0];
    const float* v      = (const float*)d_in[1];
    const float* adj    = (const float*)d_in[2];
    const float* degree = (const float*)d_in[3];
    const float* uw     = (const float*)d_in[4];
    const float* vw     = (const float*)d_in[5];
    const float* bias   = (const float*)d_in[6];
    const int*   rp     = (const int*)d_in[7];

    const int nu = in_sizes[0] / IN_DIM;   // 8192
    const int nv = in_sizes[1] / IN_DIM;   // 8192
    float* out = (float*)d_out;

    k_prep<<<64, 256>>>(uw, vw, rp);

    dim3 gf(nu / 32, 2);
    k_feat<<<gf, 256>>>(u, v, nu, nv);

    dim3 g0(nu / 128, SPLITS);
    k_gemm<0><<<g0, 256>>>(adj, nu, nv);
    dim3 g1(nv / 128, SPLITS);
    k_gemm<1><<<g1, 256>>>(adj, nu, nv);

    const int total = (nu + nv) * HID;
    k_final<<<(total + 255) / 256, 256>>>(degree, bias, out, nu, nv);
}

// round 7
// speedup vs baseline: 1.2039x; 1.2039x over previous
#include <cuda_runtime.h>
#include <cstdint>

// GraphConvolution on GB300:
//   Wu = sum_{c<=r} u_weight[c]; Wv likewise          (k_prep)
//   su/sv = (u|v) @ W  -> stored tf32-rounded, MMA-fragment-packed (k_feat)
//   top = deg[:nu] * (adj @ sv); bot = deg[nu:] * (adjT @ su)
//        -> k_gemm: ONE launch, grid (64, SPLITS, 2); blockIdx.z dispatches to a
//           compile-time-specialized body. tf32 mma.sync, 3-stage cp.async.
//   out = concat(top,bot) + bias                       (k_final)

#define IN_DIM 128
#define HID    64
#define NMAX   8192
#define SPLITS 4
#define STAGES 3

// A-tile SMEM strides (conflict-free fragment LDS, verified):
//   GZ=0 layout [m][k], stride 20  (banks 20g+t mod 32 distinct)
//   GZ=1 layout [k][m], stride 136 (banks 8t+g  mod 32 distinct)
#define AS0_STRIDE 20
#define AS1_STRIDE 136
#define AS_FLOATS  2560   // max(128*20, 16*136)
// B-tile: packed fragment layout, 16k x 64h = 1024 floats, no padding.
#define BS_FLOATS  1024

// su/sv stored packed: idx(k,h) = (k/16)*1024 + h*16 + (k%4)*4 + ((k/4)%4)
// -> LDS128 at h*16 + 4t yields k = {t, t+4, t+8, t+12} for column h.
__device__ __align__(16) float g_Wu[IN_DIM * HID];
__device__ __align__(16) float g_Wv[IN_DIM * HID];
__device__ __align__(16) float g_suB[NMAX * HID];
__device__ __align__(16) float g_svB[NMAX * HID];
__device__ __align__(16) float g_part[2 * SPLITS * NMAX * HID];

__device__ __forceinline__ float to_tf32(float x) {
    asm("cvt.rna.tf32.f32 %0, %0;" : "+f"(x));
    return x;
}
__device__ __forceinline__ uint32_t tf32_bits(float x) {
    return __float_as_uint(to_tf32(x));
}
__device__ __forceinline__ void cp16(void* dst_smem, const void* src_gmem) {
    uint32_t d = (uint32_t)__cvta_generic_to_shared(dst_smem);
    asm volatile("cp.async.cg.shared.global [%0], [%1], 16;\n" :: "r"(d), "l"(src_gmem));
}

// ---------------------------------------------------------------------------
__global__ void k_prep(const float* __restrict__ uw, const float* __restrict__ vw,
                       const int* __restrict__ rp) {
    const int r = rp[0];
    const int n = IN_DIM * HID;
    for (int i = blockIdx.x * blockDim.x + threadIdx.x; i < n; i += gridDim.x * blockDim.x) {
        float a = 0.f, b = 0.f;
        for (int c = 0; c <= r; c++) { a += uw[c * n + i]; b += vw[c * n + i]; }
        g_Wu[i] = a; g_Wv[i] = b;
    }
}

// ---------------------------------------------------------------------------
// su / sv:  X[rows,128] @ W[128,64], output tf32-rounded in packed layout.
#define WT_STRIDE 132
__global__ __launch_bounds__(256)
void k_feat(const float* __restrict__ u, const float* __restrict__ v, int nu, int nv) {
    __shared__ float Wt[HID * WT_STRIDE];   // [h][k]
    __shared__ float Us[32 * IN_DIM];
    const float* X; const float* W; float* out; int rows;
    if (blockIdx.y == 0) { X = u; W = g_Wu; out = g_suB; rows = nu; }
    else                 { X = v; W = g_Wv; out = g_svB; rows = nv; }

    const int tid = threadIdx.x;
    const int r0  = blockIdx.x * 32;
    if (r0 >= rows) return;

    for (int i = tid; i < IN_DIM * HID; i += 256) {
        const int k = i >> 6, h = i & 63;           // W is [k][h]
        Wt[h * WT_STRIDE + k] = W[i];
    }
    for (int i = tid; i < 32 * IN_DIM; i += 256)  Us[i] = X[(size_t)r0 * IN_DIM + i];
    __syncthreads();

    const int h  = tid & 63;
    const int rg = (tid >> 6) * 8;   // 8 rows per thread
    float acc[8];
    #pragma unroll
    for (int r = 0; r < 8; r++) acc[r] = 0.f;

    #pragma unroll 4
    for (int k = 0; k < IN_DIM; k += 4) {
        const float4 wq = *(const float4*)&Wt[h * WT_STRIDE + k];
        #pragma unroll
        for (int r = 0; r < 8; r++) {
            const float4 uq = *(const float4*)&Us[(rg + r) * IN_DIM + k];
            acc[r] += uq.x * wq.x + uq.y * wq.y + uq.z * wq.z + uq.w * wq.w;
        }
    }
    #pragma unroll
    for (int r = 0; r < 8; r++) {
        const int k = r0 + rg + r;   // global row index = GEMM k index
        const int idx = (k >> 4) * 1024 + h * 16 + (k & 3) * 4 + ((k >> 2) & 3);
        out[idx] = to_tf32(acc[r]);
    }
}

// ---------------------------------------------------------------------------
// GZ=0: C[m,h] = sum_k adj[m*nv + k]  * sv[k,h]
// GZ=1: C[m,h] = sum_k adj[k*nv + m]  * su[k,h]
// BM=128, BN=64, BK=16; 8 warps as 4(M)x2(N), warp 32x32 via m16n8k8 tf32.
// 3-stage cp.async pipeline (empty commit at tail keeps FIFO accounting).
template <int GZ>
__device__ __forceinline__
void gemm_body(const float* __restrict__ adj, int nu, int nv,
               float (*As)[AS_FLOATS], float (*Bs)[BS_FLOATS]) {
    const int K = GZ ? nu : nv;
    const float* __restrict__ B = GZ ? g_suB : g_svB;

    const int m0     = blockIdx.x * 128;
    const int klen   = K / SPLITS;
    const int k0     = blockIdx.y * klen;
    const int ntiles = klen / 16;

    const int tid  = threadIdx.x;
    const int warp = tid >> 5;
    const int lane = tid & 31;
    const int g    = lane >> 2;
    const int t    = lane & 3;
    const int wm   = (warp >> 1) * 32;
    const int wn   = (warp & 1) * 32;

    float acc[2][4][4];
    #pragma unroll
    for (int i = 0; i < 2; i++)
        #pragma unroll
        for (int j = 0; j < 4; j++)
            #pragma unroll
            for (int q = 0; q < 4; q++) acc[i][j][q] = 0.f;

    auto issue = [&](int s, int kt) {
        const int kbase = k0 + kt * 16;
        // B tile: 4KB contiguous packed block, 1 chunk per thread
        cp16(&Bs[s][tid * 4], &B[(size_t)(kbase >> 4) * 1024 + tid * 4]);
        if (GZ == 0) {  // A tile [m][k]
            const int r = tid >> 2, c = tid & 3;
            cp16(&As[s][r * AS0_STRIDE + c * 4],
                 &adj[(size_t)(m0 + r) * nv + kbase + c * 4]);
            cp16(&As[s][(r + 64) * AS0_STRIDE + c * 4],
                 &adj[(size_t)(m0 + r + 64) * nv + kbase + c * 4]);
        } else {        // A tile [k][m]
            const int row = tid >> 4, ch = tid & 15;
            cp16(&As[s][row * AS1_STRIDE + ch * 4],
                 &adj[(size_t)(kbase + row) * nv + m0 + ch * 4]);
            cp16(&As[s][row * AS1_STRIDE + (ch + 16) * 4],
                 &adj[(size_t)(kbase + row) * nv + m0 + (ch + 16) * 4]);
        }
        asm volatile("cp.async.commit_group;\n" ::);
    };

    #pragma unroll
    for (int s = 0; s < STAGES - 1; s++) issue(s, s);

    for (int kt = 0; kt < ntiles; kt++) {
        const int s = kt % STAGES;
        asm volatile("cp.async.wait_group %0;\n" :: "n"(STAGES - 2));
        __syncthreads();

        const int nk = kt + STAGES - 1;
        if (nk < ntiles) issue(nk % STAGES, nk);
        else             asm volatile("cp.async.commit_group;\n" ::);

        const float* __restrict__ Asb = As[s];
        const float* __restrict__ Bsb = Bs[s];

        // B fragments for all 4 ntiles, BOTH kk steps: 4 conflict-free LDS128.
        float4 bq[4];
        #pragma unroll
        for (int j = 0; j < 4; j++)
            bq[j] = *(const float4*)&Bsb[(wn + 8 * j + g) * 16 + 4 * t];

        #pragma unroll
        for (int kk = 0; kk < 16; kk += 8) {
            uint32_t af[2][4];
            #pragma unroll
            for (int i = 0; i < 2; i++) {
                const int mb = wm + i * 16 + g;
                if (GZ == 0) {
                    af[i][0] = tf32_bits(Asb[(mb)     * AS0_STRIDE + kk + t]);
                    af[i][1] = tf32_bits(Asb[(mb + 8) * AS0_STRIDE + kk + t]);
                    af[i][2] = tf32_bits(Asb[(mb)     * AS0_STRIDE + kk + t + 4]);
                    af[i][3] = tf32_bits(Asb[(mb + 8) * AS0_STRIDE + kk + t + 4]);
                } else {
                    af[i][0] = tf32_bits(Asb[(kk + t)     * AS1_STRIDE + mb]);
                    af[i][1] = tf32_bits(Asb[(kk + t)     * AS1_STRIDE + mb + 8]);
                    af[i][2] = tf32_bits(Asb[(kk + t + 4) * AS1_STRIDE + mb]);
                    af[i][3] = tf32_bits(Asb[(kk + t + 4) * AS1_STRIDE + mb + 8]);
                }
            }
            #pragma unroll
            for (int i = 0; i < 2; i++)
                #pragma unroll
                for (int j = 0; j < 4; j++) {
                    const uint32_t b0 = __float_as_uint(kk ? bq[j].z : bq[j].x);
                    const uint32_t b1 = __float_as_uint(kk ? bq[j].w : bq[j].y);
                    asm volatile(
                        "mma.sync.aligned.m16n8k8.row.col.f32.tf32.tf32.f32 "
                        "{%0,%1,%2,%3}, {%4,%5,%6,%7}, {%8,%9}, {%0,%1,%2,%3};"
                        : "+f"(acc[i][j][0]), "+f"(acc[i][j][1]),
                          "+f"(acc[i][j][2]), "+f"(acc[i][j][3])
                        : "r"(af[i][0]), "r"(af[i][1]), "r"(af[i][2]), "r"(af[i][3]),
                          "r"(b0), "r"(b1));
                }
        }
        __syncthreads();
    }

    float* __restrict__ P = &g_part[(size_t)((GZ * SPLITS + blockIdx.y) * NMAX) * HID];
    #pragma unroll
    for (int i = 0; i < 2; i++) {
        #pragma unroll
        for (int j = 0; j < 4; j++) {
            const int m = m0 + wm + i * 16 + g;
            const int n = wn + j * 8 + 2 * t;
            *(float2*)&P[(size_t)m * HID + n]       = make_float2(acc[i][j][0], acc[i][j][1]);
            *(float2*)&P[(size_t)(m + 8) * HID + n] = make_float2(acc[i][j][2], acc[i][j][3]);
        }
    }
}

// One launch covers both orientations: blockIdx.z selects the specialized body
// (single top-level branch; all inner code is compile-time GZ).
__global__ __launch_bounds__(256, 4)
void k_gemm(const float* __restrict__ adj, int nu, int nv) {
    __shared__ __align__(16) float As[STAGES][AS_FLOATS];
    __shared__ __align__(16) float Bs[STAGES][BS_FLOATS];
    if (blockIdx.z == 0) gemm_body<0>(adj, nu, nv, As, Bs);
    else                 gemm_body<1>(adj, nu, nv, As, Bs);
}

// ---------------------------------------------------------------------------
__global__ void k_final(const float* __restrict__ degree, const float* __restrict__ bias,
                        float* __restrict__ out, int nu, int nv) {
    const int total = (nu + nv) * HID;
    const int idx = blockIdx.x * blockDim.x + threadIdx.x;
    if (idx >= total) return;
    const int row = idx >> 6;
    const int h   = idx & 63;
    const int gg  = (row < nu) ? 0 : 1;
    const int rr  = gg ? (row - nu) : row;
    float s = 0.f;
    #pragma unroll
    for (int sp = 0; sp < SPLITS; sp++)
        s += g_part[((size_t)(gg * SPLITS + sp) * NMAX + rr) * HID + h];
    out[idx] = degree[row] * s + bias[h];
}

// ---------------------------------------------------------------------------
extern "C" void kernel_launch(void* const* d_in, const int* in_sizes, int n_in,
                              void* d_out, int out_size) {
    const float* u      = (const float*)d_in[0];
    const float* v      = (const float*)d_in[1];
    const float* adj    = (const float*)d_in[2];
    const float* degree = (const float*)d_in[3];
    const float* uw     = (const float*)d_in[4];
    const float* vw     = (const float*)d_in[5];
    const float* bias   = (const float*)d_in[6];
    const int*   rp     = (const int*)d_in[7];

    const int nu = in_sizes[0] / IN_DIM;   // 8192
    const int nv = in_sizes[1] / IN_DIM;   // 8192
    float* out = (float*)d_out;

    k_prep<<<64, 256>>>(uw, vw, rp);

    dim3 gf(nu / 32, 2);
    k_feat<<<gf, 256>>>(u, v, nu, nv);

    dim3 gg(nu / 128, SPLITS, 2);   // 512 CTAs: one full resident wave
    k_gemm<<<gg, 256>>>(adj, nu, nv);

    const int total = (nu + nv) * HID;
    k_final<<<(total + 255) / 256, 256>>>(degree, bias, out, nu, nv);
}

// round 10
// speedup vs baseline: 1.3518x; 1.1229x over previous
#include <cuda_runtime.h>
#include <cstdint>

// GraphConvolution on GB300 — mma.sync tf32, SMEM-byte-minimized GEMM.
//   k_prep : Wu/Wv = sum of weight slices
//   k_feat : su/sv = (u|v) @ W, tf32-RNA-rounded, MMA-fragment-packed
//   k_gemm : ONE launch grid(32, SPLITS, 2); BM=256 BN=64 BK=16, 4 warps,
//            warp=64m x 64n (A fragments read once; B dup only 4x),
//            2-stage cp.async, split-K partials.
//   k_final: partial reduce + degree scale + bias

#define IN_DIM 128
#define HID    64
#define NMAX   8192
#define SPLITS 8
#define BM     256
#define BK     16

// A-tile SMEM strides (conflict-free fragment LDS):
//   GZ=0 [m][k] stride 20  (banks 20g+t mod 32 distinct)
//   GZ=1 [k][m] stride 264 (banks 8t+g  mod 32 distinct; 264*4B mult of 16)
#define AS0_STRIDE 20
#define AS1_STRIDE 264
#define AS_FLOATS  5120          // max(256*20, 16*264)=5120 vs 4224
#define BS_FLOATS  1024          // packed B tile: 16k x 64h

// packed su/sv: idx(k,h) = (k/16)*1024 + h*16 + (k%4)*4 + ((k/4)%4)
// -> LDS128 at h*16+4t yields k = {t, t+4, t+8, t+12} for column h.
__device__ __align__(16) float g_Wu[IN_DIM * HID];
__device__ __align__(16) float g_Wv[IN_DIM * HID];
__device__ __align__(16) float g_suB[NMAX * HID];
__device__ __align__(16) float g_svB[NMAX * HID];
__device__ __align__(16) float g_part[2 * SPLITS * NMAX * HID];

__device__ __forceinline__ float to_tf32(float x) {
    asm("cvt.rna.tf32.f32 %0, %0;" : "+f"(x));
    return x;
}
__device__ __forceinline__ uint32_t tf32_bits(float x) {
    return __float_as_uint(to_tf32(x));
}
__device__ __forceinline__ void cp16(void* dst_smem, const void* src_gmem) {
    uint32_t d = (uint32_t)__cvta_generic_to_shared(dst_smem);
    asm volatile("cp.async.cg.shared.global [%0], [%1], 16;\n" :: "r"(d), "l"(src_gmem));
}

// ---------------------------------------------------------------------------
__global__ void k_prep(const float* __restrict__ uw, const float* __restrict__ vw,
                       const int* __restrict__ rp) {
    const int r = rp[0];
    const int n = IN_DIM * HID;
    for (int i = blockIdx.x * blockDim.x + threadIdx.x; i < n; i += gridDim.x * blockDim.x) {
        float a = 0.f, b = 0.f;
        for (int c = 0; c <= r; c++) { a += uw[c * n + i]; b += vw[c * n + i]; }
        g_Wu[i] = a; g_Wv[i] = b;
    }
}

// ---------------------------------------------------------------------------
#define WT_STRIDE 132
__global__ __launch_bounds__(256)
void k_feat(const float* __restrict__ u, const float* __restrict__ v, int nu, int nv) {
    __shared__ float Wt[HID * WT_STRIDE];
    __shared__ float Us[32 * IN_DIM];
    const float* X; const float* W; float* out; int rows;
    if (blockIdx.y == 0) { X = u; W = g_Wu; out = g_suB; rows = nu; }
    else                 { X = v; W = g_Wv; out = g_svB; rows = nv; }

    const int tid = threadIdx.x;
    const int r0  = blockIdx.x * 32;
    if (r0 >= rows) return;

    for (int i = tid; i < IN_DIM * HID; i += 256) {
        const int k = i >> 6, h = i & 63;
        Wt[h * WT_STRIDE + k] = W[i];
    }
    for (int i = tid; i < 32 * IN_DIM; i += 256)  Us[i] = X[(size_t)r0 * IN_DIM + i];
    __syncthreads();

    const int h  = tid & 63;
    const int rg = (tid >> 6) * 8;
    float acc[8];
    #pragma unroll
    for (int r = 0; r < 8; r++) acc[r] = 0.f;

    #pragma unroll 4
    for (int k = 0; k < IN_DIM; k += 4) {
        const float4 wq = *(const float4*)&Wt[h * WT_STRIDE + k];
        #pragma unroll
        for (int r = 0; r < 8; r++) {
            const float4 uq = *(const float4*)&Us[(rg + r) * IN_DIM + k];
            acc[r] += uq.x * wq.x + uq.y * wq.y + uq.z * wq.z + uq.w * wq.w;
        }
    }
    #pragma unroll
    for (int r = 0; r < 8; r++) {
        const int k = r0 + rg + r;
        const int idx = (k >> 4) * 1024 + h * 16 + (k & 3) * 4 + ((k >> 2) & 3);
        out[idx] = to_tf32(acc[r]);
    }
}

// ---------------------------------------------------------------------------
// GZ=0: C[m,h] = sum_k adj[m*nv+k] * sv[k,h]
// GZ=1: C[m,h] = sum_k adj[k*nv+m] * su[k,h]
// 4 warps; warp w owns m rows [64w, 64w+64), all 64 n. acc[4][8][4].
template <int GZ>
__device__ __forceinline__
void gemm_body(const float* __restrict__ adj, int nu, int nv, char* smem) {
    const int K = GZ ? nu : nv;
    const float* __restrict__ B = GZ ? g_suB : g_svB;

    constexpr int AS = GZ ? AS1_STRIDE : AS0_STRIDE;
    float* As0 = (float*)smem;
    float* As1 = As0 + AS_FLOATS;
    float* Bs0 = As1 + AS_FLOATS;
    float* Bs1 = Bs0 + BS_FLOATS;
    float* const Asb[2] = { As0, As1 };
    float* const Bsb[2] = { Bs0, Bs1 };

    const int m0     = blockIdx.x * BM;
    const int klen   = K / SPLITS;
    const int k0     = blockIdx.y * klen;
    const int ntiles = klen / BK;     // 64

    const int tid  = threadIdx.x;
    const int warp = tid >> 5;
    const int lane = tid & 31;
    const int g    = lane >> 2;
    const int t    = lane & 3;
    const int wm   = warp * 64;

    float acc[4][8][4];
    #pragma unroll
    for (int i = 0; i < 4; i++)
        #pragma unroll
        for (int j = 0; j < 8; j++)
            #pragma unroll
            for (int q = 0; q < 4; q++) acc[i][j][q] = 0.f;

    auto issue = [&](int s, int kt) {
        const int kbase = k0 + kt * BK;
        // B tile: 4KB packed contiguous, 2 chunks/thread
        #pragma unroll
        for (int i = 0; i < 2; i++) {
            const int c = tid + 128 * i;
            cp16(&Bsb[s][c * 4], &B[(size_t)(kbase >> 4) * 1024 + c * 4]);
        }
        // A tile: 16KB, 8 chunks/thread
        #pragma unroll
        for (int i = 0; i < 8; i++) {
            const int c = tid + 128 * i;
            if (GZ == 0) {        // [m][k]: row=c>>2 (0..255), col4=c&3
                const int r = c >> 2, c4 = c & 3;
                cp16(&Asb[s][r * AS0_STRIDE + c4 * 4],
                     &adj[(size_t)(m0 + r) * nv + kbase + c4 * 4]);
            } else {              // [k][m]: row=c>>6 (0..15), col4=c&63
                const int r = c >> 6, c4 = c & 63;
                cp16(&Asb[s][r * AS1_STRIDE + c4 * 4],
                     &adj[(size_t)(kbase + r) * nv + m0 + c4 * 4]);
            }
        }
        asm volatile("cp.async.commit_group;\n" ::);
    };

    issue(0, 0);
    issue(1, 1);

    for (int kt = 0; kt < ntiles; kt++) {
        const int s = kt & 1;
        asm volatile("cp.async.wait_group 1;\n" ::);
        __syncthreads();

        const float* __restrict__ Ab = Asb[s];
        const float* __restrict__ Bb = Bsb[s];

        // B fragments: 8 LDS128, conflict-free, cover all n & both kk steps.
        float4 bq[8];
        #pragma unroll
        for (int j = 0; j < 8; j++)
            bq[j] = *(const float4*)&Bb[(8 * j + g) * 16 + 4 * t];

        #pragma unroll
        for (int kk = 0; kk < 16; kk += 8) {
            uint32_t af[4][4];
            #pragma unroll
            for (int i = 0; i < 4; i++) {
                const int mb = wm + i * 16 + g;
                if (GZ == 0) {
                    af[i][0] = tf32_bits(Ab[(mb)     * AS + kk + t]);
                    af[i][1] = tf32_bits(Ab[(mb + 8) * AS + kk + t]);
                    af[i][2] = tf32_bits(Ab[(mb)     * AS + kk + t + 4]);
                    af[i][3] = tf32_bits(Ab[(mb + 8) * AS + kk + t + 4]);
                } else {
                    af[i][0] = tf32_bits(Ab[(kk + t)     * AS + mb]);
                    af[i][1] = tf32_bits(Ab[(kk + t)     * AS + mb + 8]);
                    af[i][2] = tf32_bits(Ab[(kk + t + 4) * AS + mb]);
                    af[i][3] = tf32_bits(Ab[(kk + t + 4) * AS + mb + 8]);
                }
            }
            #pragma unroll
            for (int i = 0; i < 4; i++)
                #pragma unroll
                for (int j = 0; j < 8; j++) {
                    const uint32_t b0 = __float_as_uint(kk ? bq[j].z : bq[j].x);
                    const uint32_t b1 = __float_as_uint(kk ? bq[j].w : bq[j].y);
                    asm volatile(
                        "mma.sync.aligned.m16n8k8.row.col.f32.tf32.tf32.f32 "
                        "{%0,%1,%2,%3}, {%4,%5,%6,%7}, {%8,%9}, {%0,%1,%2,%3};"
                        : "+f"(acc[i][j][0]), "+f"(acc[i][j][1]),
                          "+f"(acc[i][j][2]), "+f"(acc[i][j][3])
                        : "r"(af[i][0]), "r"(af[i][1]), "r"(af[i][2]), "r"(af[i][3]),
                          "r"(b0), "r"(b1));
                }
        }
        __syncthreads();

        if (kt + 2 < ntiles) issue(s, kt + 2);
        else asm volatile("cp.async.commit_group;\n" ::);   // FIFO padding
    }

    float* __restrict__ P = &g_part[(size_t)((GZ * SPLITS + blockIdx.y) * NMAX) * HID];
    #pragma unroll
    for (int i = 0; i < 4; i++) {
        #pragma unroll
        for (int j = 0; j < 8; j++) {
            const int m = m0 + wm + i * 16 + g;
            const int n = j * 8 + 2 * t;
            *(float2*)&P[(size_t)m * HID + n]       = make_float2(acc[i][j][0], acc[i][j][1]);
            *(float2*)&P[(size_t)(m + 8) * HID + n] = make_float2(acc[i][j][2], acc[i][j][3]);
        }
    }
}

__global__ __launch_bounds__(128)
void k_gemm(const float* __restrict__ adj, int nu, int nv) {
    __shared__ __align__(16) char smem[(2 * AS_FLOATS + 2 * BS_FLOATS) * 4];  // 48KB
    if (blockIdx.z == 0) gemm_body<0>(adj, nu, nv, smem);
    else                 gemm_body<1>(adj, nu, nv, smem);
}

// ---------------------------------------------------------------------------
__global__ void k_final(const float* __restrict__ degree, const float* __restrict__ bias,
                        float* __restrict__ out, int nu, int nv) {
    const int total = (nu + nv) * HID;
    const int idx = blockIdx.x * blockDim.x + threadIdx.x;
    if (idx >= total) return;
    const int row = idx >> 6;
    const int h   = idx & 63;
    const int gg  = (row < nu) ? 0 : 1;
    const int rr  = gg ? (row - nu) : row;
    float s = 0.f;
    #pragma unroll
    for (int sp = 0; sp < SPLITS; sp++)
        s += g_part[((size_t)(gg * SPLITS + sp) * NMAX + rr) * HID + h];
    out[idx] = degree[row] * s + bias[h];
}

// ---------------------------------------------------------------------------
extern "C" void kernel_launch(void* const* d_in, const int* in_sizes, int n_in,
                              void* d_out, int out_size) {
    const float* u      = (const float*)d_in[0];
    const float* v      = (const float*)d_in[1];
    const float* adj    = (const float*)d_in[2];
    const float* degree = (const float*)d_in[3];
    const float* uw     = (const float*)d_in[4];
    const float* vw     = (const float*)d_in[5];
    const float* bias   = (const float*)d_in[6];
    const int*   rp     = (const int*)d_in[7];

    const int nu = in_sizes[0] / IN_DIM;   // 8192
    const int nv = in_sizes[1] / IN_DIM;   // 8192
    float* out = (float*)d_out;

    k_prep<<<64, 256>>>(uw, vw, rp);

    dim3 gf(nu / 32, 2);
    k_feat<<<gf, 256>>>(u, v, nu, nv);

    dim3 gg(nu / BM, SPLITS, 2);   // (32, 8, 2) = 512 CTAs
    k_gemm<<<gg, 128>>>(adj, nu, nv);

    const int total = (nu + nv) * HID;
    k_final<<<(total + 255) / 256, 256>>>(degree, bias, out, nu, nv);
}

// round 11
// speedup vs baseline: 1.4236x; 1.0531x over previous
#include <cuda_runtime.h>
#include <cstdint>

// GraphConvolution on GB300 — mma.sync tf32, SMEM-byte-minimized GEMM.
//   k_prep : Wu/Wv = sum of weight slices
//   k_feat : su/sv = (u|v) @ W, tf32-RNA-rounded, MMA-fragment-packed
//   k_gemm : ONE launch grid(32, SPLITS, 2); BM=256 BN=64 BK=16, 4 warps,
//            warp=64m x 64n (A fragments read once; B dup only 4x),
//            2-stage cp.async, split-K partials. A operand fed as RAW fp32
//            bits (HW tf32 truncation) — saves 32 CVT/warp/tile.
//   k_final: partial reduce + degree scale + bias

#define IN_DIM 128
#define HID    64
#define NMAX   8192
#define SPLITS 4
#define BM     256
#define BK     16

// A-tile SMEM strides (conflict-free fragment LDS):
//   GZ=0 [m][k] stride 20  (banks 20g+t mod 32 distinct)
//   GZ=1 [k][m] stride 264 (banks 8t+g  mod 32 distinct; 264*4B mult of 16)
#define AS0_STRIDE 20
#define AS1_STRIDE 264
#define AS_FLOATS  5120
#define BS_FLOATS  1024          // packed B tile: 16k x 64h

// packed su/sv: idx(k,h) = (k/16)*1024 + h*16 + (k%4)*4 + ((k/4)%4)
// -> LDS128 at h*16+4t yields k = {t, t+4, t+8, t+12} for column h.
__device__ __align__(16) float g_Wu[IN_DIM * HID];
__device__ __align__(16) float g_Wv[IN_DIM * HID];
__device__ __align__(16) float g_suB[NMAX * HID];
__device__ __align__(16) float g_svB[NMAX * HID];
__device__ __align__(16) float g_part[2 * SPLITS * NMAX * HID];

__device__ __forceinline__ float to_tf32(float x) {
    asm("cvt.rna.tf32.f32 %0, %0;" : "+f"(x));
    return x;
}
__device__ __forceinline__ void cp16(void* dst_smem, const void* src_gmem) {
    uint32_t d = (uint32_t)__cvta_generic_to_shared(dst_smem);
    asm volatile("cp.async.cg.shared.global [%0], [%1], 16;\n" :: "r"(d), "l"(src_gmem));
}

// ---------------------------------------------------------------------------
__global__ void k_prep(const float* __restrict__ uw, const float* __restrict__ vw,
                       const int* __restrict__ rp) {
    const int r = rp[0];
    const int n = IN_DIM * HID;
    for (int i = blockIdx.x * blockDim.x + threadIdx.x; i < n; i += gridDim.x * blockDim.x) {
        float a = 0.f, b = 0.f;
        for (int c = 0; c <= r; c++) { a += uw[c * n + i]; b += vw[c * n + i]; }
        g_Wu[i] = a; g_Wv[i] = b;
    }
}

// ---------------------------------------------------------------------------
#define WT_STRIDE 132
__global__ __launch_bounds__(256)
void k_feat(const float* __restrict__ u, const float* __restrict__ v, int nu, int nv) {
    __shared__ float Wt[HID * WT_STRIDE];
    __shared__ float Us[32 * IN_DIM];
    const float* X; const float* W; float* out; int rows;
    if (blockIdx.y == 0) { X = u; W = g_Wu; out = g_suB; rows = nu; }
    else                 { X = v; W = g_Wv; out = g_svB; rows = nv; }

    const int tid = threadIdx.x;
    const int r0  = blockIdx.x * 32;
    if (r0 >= rows) return;

    for (int i = tid; i < IN_DIM * HID; i += 256) {
        const int k = i >> 6, h = i & 63;
        Wt[h * WT_STRIDE + k] = W[i];
    }
    for (int i = tid; i < 32 * IN_DIM; i += 256)  Us[i] = X[(size_t)r0 * IN_DIM + i];
    __syncthreads();

    const int h  = tid & 63;
    const int rg = (tid >> 6) * 8;
    float acc[8];
    #pragma unroll
    for (int r = 0; r < 8; r++) acc[r] = 0.f;

    #pragma unroll 4
    for (int k = 0; k < IN_DIM; k += 4) {
        const float4 wq = *(const float4*)&Wt[h * WT_STRIDE + k];
        #pragma unroll
        for (int r = 0; r < 8; r++) {
            const float4 uq = *(const float4*)&Us[(rg + r) * IN_DIM + k];
            acc[r] += uq.x * wq.x + uq.y * wq.y + uq.z * wq.z + uq.w * wq.w;
        }
    }
    #pragma unroll
    for (int r = 0; r < 8; r++) {
        const int k = r0 + rg + r;
        const int idx = (k >> 4) * 1024 + h * 16 + (k & 3) * 4 + ((k >> 2) & 3);
        out[idx] = to_tf32(acc[r]);
    }
}

// ---------------------------------------------------------------------------
// GZ=0: C[m,h] = sum_k adj[m*nv+k] * sv[k,h]
// GZ=1: C[m,h] = sum_k adj[k*nv+m] * su[k,h]
// 4 warps; warp w owns m rows [64w, 64w+64), all 64 n. acc[4][8][4].
template <int GZ>
__device__ __forceinline__
void gemm_body(const float* __restrict__ adj, int nu, int nv, char* smem) {
    const int K = GZ ? nu : nv;
    const float* __restrict__ B = GZ ? g_suB : g_svB;

    constexpr int AS = GZ ? AS1_STRIDE : AS0_STRIDE;
    float* As0 = (float*)smem;
    float* As1 = As0 + AS_FLOATS;
    float* Bs0 = As1 + AS_FLOATS;
    float* Bs1 = Bs0 + BS_FLOATS;
    float* const Asb[2] = { As0, As1 };
    float* const Bsb[2] = { Bs0, Bs1 };

    const int m0     = blockIdx.x * BM;
    const int klen   = K / SPLITS;
    const int k0     = blockIdx.y * klen;
    const int ntiles = klen / BK;

    const int tid  = threadIdx.x;
    const int warp = tid >> 5;
    const int lane = tid & 31;
    const int g    = lane >> 2;
    const int t    = lane & 3;
    const int wm   = warp * 64;

    float acc[4][8][4];
    #pragma unroll
    for (int i = 0; i < 4; i++)
        #pragma unroll
        for (int j = 0; j < 8; j++)
            #pragma unroll
            for (int q = 0; q < 4; q++) acc[i][j][q] = 0.f;

    auto issue = [&](int s, int kt) {
        const int kbase = k0 + kt * BK;
        #pragma unroll
        for (int i = 0; i < 2; i++) {
            const int c = tid + 128 * i;
            cp16(&Bsb[s][c * 4], &B[(size_t)(kbase >> 4) * 1024 + c * 4]);
        }
        #pragma unroll
        for (int i = 0; i < 8; i++) {
            const int c = tid + 128 * i;
            if (GZ == 0) {
                const int r = c >> 2, c4 = c & 3;
                cp16(&Asb[s][r * AS0_STRIDE + c4 * 4],
                     &adj[(size_t)(m0 + r) * nv + kbase + c4 * 4]);
            } else {
                const int r = c >> 6, c4 = c & 63;
                cp16(&Asb[s][r * AS1_STRIDE + c4 * 4],
                     &adj[(size_t)(kbase + r) * nv + m0 + c4 * 4]);
            }
        }
        asm volatile("cp.async.commit_group;\n" ::);
    };

    issue(0, 0);
    issue(1, 1);

    for (int kt = 0; kt < ntiles; kt++) {
        const int s = kt & 1;
        asm volatile("cp.async.wait_group 1;\n" ::);
        __syncthreads();

        const float* __restrict__ Ab = Asb[s];
        const float* __restrict__ Bb = Bsb[s];

        float4 bq[8];
        #pragma unroll
        for (int j = 0; j < 8; j++)
            bq[j] = *(const float4*)&Bb[(8 * j + g) * 16 + 4 * t];

        #pragma unroll
        for (int kk = 0; kk < 16; kk += 8) {
            uint32_t af[4][4];
            #pragma unroll
            for (int i = 0; i < 4; i++) {
                const int mb = wm + i * 16 + g;
                // RAW fp32 bits: mma tf32 path truncates the mantissa in HW.
                if (GZ == 0) {
                    af[i][0] = __float_as_uint(Ab[(mb)     * AS + kk + t]);
                    af[i][1] = __float_as_uint(Ab[(mb + 8) * AS + kk + t]);
                    af[i][2] = __float_as_uint(Ab[(mb)     * AS + kk + t + 4]);
                    af[i][3] = __float_as_uint(Ab[(mb + 8) * AS + kk + t + 4]);
                } else {
                    af[i][0] = __float_as_uint(Ab[(kk + t)     * AS + mb]);
                    af[i][1] = __float_as_uint(Ab[(kk + t)     * AS + mb + 8]);
                    af[i][2] = __float_as_uint(Ab[(kk + t + 4) * AS + mb]);
                    af[i][3] = __float_as_uint(Ab[(kk + t + 4) * AS + mb + 8]);
                }
            }
            #pragma unroll
            for (int i = 0; i < 4; i++)
                #pragma unroll
                for (int j = 0; j < 8; j++) {
                    const uint32_t b0 = __float_as_uint(kk ? bq[j].z : bq[j].x);
                    const uint32_t b1 = __float_as_uint(kk ? bq[j].w : bq[j].y);
                    asm volatile(
                        "mma.sync.aligned.m16n8k8.row.col.f32.tf32.tf32.f32 "
                        "{%0,%1,%2,%3}, {%4,%5,%6,%7}, {%8,%9}, {%0,%1,%2,%3};"
                        : "+f"(acc[i][j][0]), "+f"(acc[i][j][1]),
                          "+f"(acc[i][j][2]), "+f"(acc[i][j][3])
                        : "r"(af[i][0]), "r"(af[i][1]), "r"(af[i][2]), "r"(af[i][3]),
                          "r"(b0), "r"(b1));
                }
        }
        __syncthreads();

        if (kt + 2 < ntiles) issue(s, kt + 2);
        else asm volatile("cp.async.commit_group;\n" ::);   // FIFO padding
    }

    float* __restrict__ P = &g_part[(size_t)((GZ * SPLITS + blockIdx.y) * NMAX) * HID];
    #pragma unroll
    for (int i = 0; i < 4; i++) {
        #pragma unroll
        for (int j = 0; j < 8; j++) {
            const int m = m0 + wm + i * 16 + g;
            const int n = j * 8 + 2 * t;
            *(float2*)&P[(size_t)m * HID + n]       = make_float2(acc[i][j][0], acc[i][j][1]);
            *(float2*)&P[(size_t)(m + 8) * HID + n] = make_float2(acc[i][j][2], acc[i][j][3]);
        }
    }
}

__global__ __launch_bounds__(128)
void k_gemm(const float* __restrict__ adj, int nu, int nv) {
    __shared__ __align__(16) char smem[(2 * AS_FLOATS + 2 * BS_FLOATS) * 4];  // 48KB
    if (blockIdx.z == 0) gemm_body<0>(adj, nu, nv, smem);
    else                 gemm_body<1>(adj, nu, nv, smem);
}

// ---------------------------------------------------------------------------
__global__ void k_final(const float* __restrict__ degree, const float* __restrict__ bias,
                        float* __restrict__ out, int nu, int nv) {
    const int total = (nu + nv) * HID;
    const int idx = blockIdx.x * blockDim.x + threadIdx.x;
    if (idx >= total) return;
    const int row = idx >> 6;
    const int h   = idx & 63;
    const int gg  = (row < nu) ? 0 : 1;
    const int rr  = gg ? (row - nu) : row;
    float s = 0.f;
    #pragma unroll
    for (int sp = 0; sp < SPLITS; sp++)
        s += g_part[((size_t)(gg * SPLITS + sp) * NMAX + rr) * HID + h];
    out[idx] = degree[row] * s + bias[h];
}

// ---------------------------------------------------------------------------
extern "C" void kernel_launch(void* const* d_in, const int* in_sizes, int n_in,
                              void* d_out, int out_size) {
    const float* u      = (const float*)d_in[0];
    const float* v      = (const float*)d_in[1];
    const float* adj    = (const float*)d_in[2];
    const float* degree = (const float*)d_in[3];
    const float* uw     = (const float*)d_in[4];
    const float* vw     = (const float*)d_in[5];
    const float* bias   = (const float*)d_in[6];
    const int*   rp     = (const int*)d_in[7];

    const int nu = in_sizes[0] / IN_DIM;   // 8192
    const int nv = in_sizes[1] / IN_DIM;   // 8192
    float* out = (float*)d_out;

    k_prep<<<64, 256>>>(uw, vw, rp);

    dim3 gf(nu / 32, 2);
    k_feat<<<gf, 256>>>(u, v, nu, nv);

    dim3 gg(nu / BM, SPLITS, 2);   // (32, 4, 2) = 256 CTAs, one resident wave
    k_gemm<<<gg, 128>>>(adj, nu, nv);

    const int total = (nu + nv) * HID;
    k_final<<<(total + 255) / 256, 256>>>(degree, bias, out, nu, nv);
}

// round 12
// speedup vs baseline: 1.4894x; 1.0462x over previous
#include <cuda_runtime.h>
#include <cstdint>

// GraphConvolution on GB300 — fp16 m16n8k16 mma.sync (2x legacy-tensor rate vs tf32).
//   k_prep : Wu/Wv = sum of weight slices
//   k_feat : su/sv = (u|v) @ W, packed as fp16 pairs in MMA B-fragment order
//   k_gemm : ONE launch grid(32, SPLITS, 2); BM=256 BN=64 BK=16, 4 warps,
//            warp=64m x 64n. A kept fp32 in SMEM (same verified conflict-free
//            layout); fragments packed to fp16 at load (k-slot permutation
//            (2t,2t+1,2t+8,2t+9) -> logical (t,t+8,t+4,t+12), matched by B).
//   k_final: partial reduce + degree scale + bias

#define IN_DIM 128
#define HID    64
#define NMAX   8192
#define SPLITS 4
#define BM     256
#define BK     16

// A-tile SMEM strides (conflict-free scalar fragment LDS, verified):
//   GZ=0 [m][k] stride 20  (banks 20g+t+c mod 32 distinct, c in {0,4,8,12})
//   GZ=1 [k][m] stride 264 (banks 8t+g  mod 32 distinct)
#define AS0_STRIDE 20
#define AS1_STRIDE 264
#define AS_FLOATS  5120
#define BS_U32     512     // B tile: 16k x 64h fp16 = 512 u32, frag-packed

// B packed layout (u32): idx = (k/16)*512 + t*128 + h*2 + sel
//   sel=0 u32 = halfs (logical k = t,   t+8 )   t = frag thread-in-group
//   sel=1 u32 = halfs (logical k = t+4, t+12)
// Frag load: uint2 at t*128 + h*2 -> banks (2g+16j) mod 32, 4-lane broadcast,
// conflict-free.
__device__ __align__(16) float    g_Wu[IN_DIM * HID];
__device__ __align__(16) float    g_Wv[IN_DIM * HID];
__device__ __align__(16) uint32_t g_suB[NMAX * HID / 2];
__device__ __align__(16) uint32_t g_svB[NMAX * HID / 2];
__device__ __align__(16) float    g_part[2 * SPLITS * NMAX * HID];

__device__ __forceinline__ uint32_t pack_h2(float lo, float hi) {
    uint32_t r;   // PTX cvt.f16x2: first source -> HIGH half
    asm("cvt.rn.f16x2.f32 %0, %1, %2;" : "=r"(r) : "f"(hi), "f"(lo));
    return r;
}
__device__ __forceinline__ void cp16(void* dst_smem, const void* src_gmem) {
    uint32_t d = (uint32_t)__cvta_generic_to_shared(dst_smem);
    asm volatile("cp.async.cg.shared.global [%0], [%1], 16;\n" :: "r"(d), "l"(src_gmem));
}

// ---------------------------------------------------------------------------
__global__ void k_prep(const float* __restrict__ uw, const float* __restrict__ vw,
                       const int* __restrict__ rp) {
    const int r = rp[0];
    const int n = IN_DIM * HID;
    for (int i = blockIdx.x * blockDim.x + threadIdx.x; i < n; i += gridDim.x * blockDim.x) {
        float a = 0.f, b = 0.f;
        for (int c = 0; c <= r; c++) { a += uw[c * n + i]; b += vw[c * n + i]; }
        g_Wu[i] = a; g_Wv[i] = b;
    }
}

// ---------------------------------------------------------------------------
// su/sv = X @ W; each thread produces 4 (k, k+8) row-pairs for one h column,
// packing each pair into one fp16x2 u32 in B-fragment order.
#define WT_STRIDE 132
__global__ __launch_bounds__(256)
void k_feat(const float* __restrict__ u, const float* __restrict__ v, int nu, int nv) {
    __shared__ float Wt[HID * WT_STRIDE];
    __shared__ float Us[32 * IN_DIM];
    const float* X; const float* W; uint32_t* out; int rows;
    if (blockIdx.y == 0) { X = u; W = g_Wu; out = g_suB; rows = nu; }
    else                 { X = v; W = g_Wv; out = g_svB; rows = nv; }

    const int tid = threadIdx.x;
    const int r0  = blockIdx.x * 32;
    if (r0 >= rows) return;

    for (int i = tid; i < IN_DIM * HID; i += 256) {
        const int k = i >> 6, h = i & 63;
        Wt[h * WT_STRIDE + k] = W[i];
    }
    for (int i = tid; i < 32 * IN_DIM; i += 256)  Us[i] = X[(size_t)r0 * IN_DIM + i];
    __syncthreads();

    const int h   = tid & 63;
    const int q   = tid >> 6;        // 0..3
    const int b16 = q >> 1;          // which 16-row block of the 32
    const int tq  = (q & 1) * 4;     // tt base: 0 or 4

    // rows handled: local lo(i) = 16*b16 + tq + i, hi(i) = lo(i) + 8, i=0..3
    float accLo[4], accHi[4];
    #pragma unroll
    for (int i = 0; i < 4; i++) { accLo[i] = 0.f; accHi[i] = 0.f; }

    #pragma unroll 4
    for (int k = 0; k < IN_DIM; k += 4) {
        const float4 wq = *(const float4*)&Wt[h * WT_STRIDE + k];
        #pragma unroll
        for (int i = 0; i < 4; i++) {
            const int rl = 16 * b16 + tq + i;
            const float4 ulo = *(const float4*)&Us[rl * IN_DIM + k];
            const float4 uhi = *(const float4*)&Us[(rl + 8) * IN_DIM + k];
            accLo[i] += ulo.x * wq.x + ulo.y * wq.y + ulo.z * wq.z + ulo.w * wq.w;
            accHi[i] += uhi.x * wq.x + uhi.y * wq.y + uhi.z * wq.z + uhi.w * wq.w;
        }
    }
    const int kb = (r0 >> 4) + b16;          // global 16-row block index
    #pragma unroll
    for (int i = 0; i < 4; i++) {
        const int tt  = tq + i;              // 0..7
        const int sel = tt >> 2;             // 0: (t,t+8), 1: (t+4,t+12)
        const int t_  = tt & 3;
        out[(size_t)kb * 512 + t_ * 128 + h * 2 + sel] = pack_h2(accLo[i], accHi[i]);
    }
}

// ---------------------------------------------------------------------------
// GZ=0: C[m,h] = sum_k adj[m*nv+k] * sv[k,h]
// GZ=1: C[m,h] = sum_k adj[k*nv+m] * su[k,h]
template <int GZ>
__device__ __forceinline__
void gemm_body(const float* __restrict__ adj, int nu, int nv, char* smem) {
    const int K = GZ ? nu : nv;
    const uint32_t* __restrict__ B = GZ ? g_suB : g_svB;

    constexpr int AS = GZ ? AS1_STRIDE : AS0_STRIDE;
    float* As0 = (float*)smem;
    float* As1 = As0 + AS_FLOATS;
    uint32_t* Bs0 = (uint32_t*)(As1 + AS_FLOATS);
    uint32_t* Bs1 = Bs0 + BS_U32;
    float*    const Asb[2] = { As0, As1 };
    uint32_t* const Bsb[2] = { Bs0, Bs1 };

    const int m0     = blockIdx.x * BM;
    const int klen   = K / SPLITS;
    const int k0     = blockIdx.y * klen;
    const int ntiles = klen / BK;

    const int tid  = threadIdx.x;
    const int warp = tid >> 5;
    const int lane = tid & 31;
    const int g    = lane >> 2;
    const int t    = lane & 3;
    const int wm   = warp * 64;

    float acc[4][8][4];
    #pragma unroll
    for (int i = 0; i < 4; i++)
        #pragma unroll
        for (int j = 0; j < 8; j++)
            #pragma unroll
            for (int q = 0; q < 4; q++) acc[i][j][q] = 0.f;

    auto issue = [&](int s, int kt) {
        const int kbase = k0 + kt * BK;
        // B tile: 2KB packed, 1 chunk (4 u32) per thread
        cp16(&Bsb[s][tid * 4], &B[(size_t)(kbase >> 4) * 512 + tid * 4]);
        // A tile: 16KB fp32, 8 chunks per thread
        #pragma unroll
        for (int i = 0; i < 8; i++) {
            const int c = tid + 128 * i;
            if (GZ == 0) {
                const int r = c >> 2, c4 = c & 3;
                cp16(&Asb[s][r * AS0_STRIDE + c4 * 4],
                     &adj[(size_t)(m0 + r) * nv + kbase + c4 * 4]);
            } else {
                const int r = c >> 6, c4 = c & 63;
                cp16(&Asb[s][r * AS1_STRIDE + c4 * 4],
                     &adj[(size_t)(kbase + r) * nv + m0 + c4 * 4]);
            }
        }
        asm volatile("cp.async.commit_group;\n" ::);
    };

    issue(0, 0);
    issue(1, 1);

    for (int kt = 0; kt < ntiles; kt++) {
        const int s = kt & 1;
        asm volatile("cp.async.wait_group 1;\n" ::);
        __syncthreads();

        const float*    __restrict__ Ab = Asb[s];
        const uint32_t* __restrict__ Bb = Bsb[s];

        // B fragments: 8 conflict-free uint2 loads (broadcast within groups).
        uint2 bf[8];
        #pragma unroll
        for (int j = 0; j < 8; j++)
            bf[j] = *(const uint2*)&Bb[t * 128 + (8 * j + g) * 2];

        // A fragments: same verified scalar LDS addresses as the tf32 kernel,
        // packed to fp16 pairs (slot permutation matched by B's producer).
        uint32_t af[4][4];
        #pragma unroll
        for (int i = 0; i < 4; i++) {
            const int mb = wm + i * 16 + g;
            float lo0, lo8, hi0, hi8, lo4, lo12, hi4, hi12;
            if (GZ == 0) {
                lo0  = Ab[(mb)     * AS + t];      lo8  = Ab[(mb)     * AS + t + 8];
                hi0  = Ab[(mb + 8) * AS + t];      hi8  = Ab[(mb + 8) * AS + t + 8];
                lo4  = Ab[(mb)     * AS + t + 4];  lo12 = Ab[(mb)     * AS + t + 12];
                hi4  = Ab[(mb + 8) * AS + t + 4];  hi12 = Ab[(mb + 8) * AS + t + 12];
            } else {
                lo0  = Ab[(t)      * AS + mb];     lo8  = Ab[(t + 8)  * AS + mb];
                hi0  = Ab[(t)      * AS + mb + 8]; hi8  = Ab[(t + 8)  * AS + mb + 8];
                lo4  = Ab[(t + 4)  * AS + mb];     lo12 = Ab[(t + 12) * AS + mb];
                hi4  = Ab[(t + 4)  * AS + mb + 8]; hi12 = Ab[(t + 12) * AS + mb + 8];
            }
            af[i][0] = pack_h2(lo0, lo8);    // slots (2t,2t+1)   = k (t, t+8)
            af[i][1] = pack_h2(hi0, hi8);    // row+8
            af[i][2] = pack_h2(lo4, lo12);   // slots (2t+8,2t+9) = k (t+4, t+12)
            af[i][3] = pack_h2(hi4, hi12);
        }

        #pragma unroll
        for (int i = 0; i < 4; i++)
            #pragma unroll
            for (int j = 0; j < 8; j++) {
                asm volatile(
                    "mma.sync.aligned.m16n8k16.row.col.f32.f16.f16.f32 "
                    "{%0,%1,%2,%3}, {%4,%5,%6,%7}, {%8,%9}, {%0,%1,%2,%3};"
                    : "+f"(acc[i][j][0]), "+f"(acc[i][j][1]),
                      "+f"(acc[i][j][2]), "+f"(acc[i][j][3])
                    : "r"(af[i][0]), "r"(af[i][1]), "r"(af[i][2]), "r"(af[i][3]),
                      "r"(bf[j].x), "r"(bf[j].y));
            }
        __syncthreads();

        if (kt + 2 < ntiles) issue(s, kt + 2);
        else asm volatile("cp.async.commit_group;\n" ::);   // FIFO padding
    }

    float* __restrict__ P = &g_part[(size_t)((GZ * SPLITS + blockIdx.y) * NMAX) * HID];
    #pragma unroll
    for (int i = 0; i < 4; i++) {
        #pragma unroll
        for (int j = 0; j < 8; j++) {
            const int m = m0 + wm + i * 16 + g;
            const int n = j * 8 + 2 * t;
            *(float2*)&P[(size_t)m * HID + n]       = make_float2(acc[i][j][0], acc[i][j][1]);
            *(float2*)&P[(size_t)(m + 8) * HID + n] = make_float2(acc[i][j][2], acc[i][j][3]);
        }
    }
}

__global__ __launch_bounds__(128)
void k_gemm(const float* __restrict__ adj, int nu, int nv) {
    __shared__ __align__(16) char smem[(2 * AS_FLOATS) * 4 + (2 * BS_U32) * 4];  // ~44KB
    if (blockIdx.z == 0) gemm_body<0>(adj, nu, nv, smem);
    else                 gemm_body<1>(adj, nu, nv, smem);
}

// ---------------------------------------------------------------------------
__global__ void k_final(const float* __restrict__ degree, const float* __restrict__ bias,
                        float* __restrict__ out, int nu, int nv) {
    const int total = (nu + nv) * HID;
    const int idx = blockIdx.x * blockDim.x + threadIdx.x;
    if (idx >= total) return;
    const int row = idx >> 6;
    const int h   = idx & 63;
    const int gg  = (row < nu) ? 0 : 1;
    const int rr  = gg ? (row - nu) : row;
    float s = 0.f;
    #pragma unroll
    for (int sp = 0; sp < SPLITS; sp++)
        s += g_part[((size_t)(gg * SPLITS + sp) * NMAX + rr) * HID + h];
    out[idx] = degree[row] * s + bias[h];
}

// ---------------------------------------------------------------------------
extern "C" void kernel_launch(void* const* d_in, const int* in_sizes, int n_in,
                              void* d_out, int out_size) {
    const float* u      = (const float*)d_in[0];
    const float* v      = (const float*)d_in[1];
    const float* adj    = (const float*)d_in[2];
    const float* degree = (const float*)d_in[3];
    const float* uw     = (const float*)d_in[4];
    const float* vw     = (const float*)d_in[5];
    const float* bias   = (const float*)d_in[6];
    const int*   rp     = (const int*)d_in[7];

    const int nu = in_sizes[0] / IN_DIM;   // 8192
    const int nv = in_sizes[1] / IN_DIM;   // 8192
    float* out = (float*)d_out;

    k_prep<<<64, 256>>>(uw, vw, rp);

    dim3 gf(nu / 32, 2);
    k_feat<<<gf, 256>>>(u, v, nu, nv);

    dim3 gg(nu / BM, SPLITS, 2);   // (32, 4, 2) = 256 CTAs
    k_gemm<<<gg, 128>>>(adj, nu, nv);

    const int total = (nu + nv) * HID;
    k_final<<<(total + 255) / 256, 256>>>(degree, bias, out, nu, nv);
}